// round 9
// baseline (speedup 1.0000x reference)
#include <cuda_runtime.h>
#include <cuda_bf16.h>
#include <math.h>

#define NN 100000
#define EE 1600000
#define HH 128
#define GG 64
#define COLCAP (EE + 7 * NN + 8)

// ---------- device scratch ----------
__device__ int   g_degcnt[NN];
__device__ float g_dinv[NN];
__device__ int   g_rowptr[NN + 1];
__device__ int   g_cursor[NN];
__device__ int   g_colsrc[COLCAP];
__device__ __align__(16) __nv_bfloat16 g_bufA[(size_t)(NN + 1) * HH];  // +1 dummy zero row
__device__ __align__(16) __nv_bfloat16 g_bufB[(size_t)NN * HH];
__device__ __align__(16) __nv_bfloat16 g_bufX[(size_t)NN * HH];
__device__ __align__(16) __nv_bfloat16 g_whi[3][HH * HH];   // Wt_hi[n][k]
__device__ __align__(16) __nv_bfloat16 g_wlo[3][HH * HH];   // Wt_lo[n][k]
__device__ float g_sums[GG * HH];
__device__ int   g_cnt[GG];

// ---------- helpers ----------
__device__ __forceinline__ float2 bf2f(unsigned int v) {
    __nv_bfloat162 b = *reinterpret_cast<__nv_bfloat162*>(&v);
    return __bfloat1622float2(b);
}
__device__ __forceinline__ unsigned int f2bf(float a, float b) {
    __nv_bfloat162 r = __float22bfloat162_rn(make_float2(a, b));
    return *reinterpret_cast<unsigned int*>(&r);
}
__device__ __forceinline__ float elu_f(float x) { return x > 0.f ? x : expm1f(x); }

// ---------- 1. zero scratch + pad-row init ----------
__global__ void k_init() {
    int i = blockIdx.x * blockDim.x + threadIdx.x;
    int stride = gridDim.x * blockDim.x;
    for (int j = i; j < NN; j += stride) g_degcnt[j] = 0;
    for (int j = i; j < COLCAP; j += stride) g_colsrc[j] = NN;   // pad slots -> dummy row
    for (int j = i; j < GG * HH; j += stride) g_sums[j] = 0.f;
    for (int j = i; j < GG; j += stride) g_cnt[j] = 0;
    for (int j = i; j < HH; j += stride) g_bufA[(size_t)NN * HH + j] = __float2bfloat16(0.f);
}

// ---------- 2. in-degree histogram ----------
__global__ void k_hist(const int* __restrict__ dst) {
    int i = blockIdx.x * 256 + threadIdx.x;
    if (i < EE) atomicAdd(&g_degcnt[dst[i]], 1);
}

// ---------- 3. scan (8-padded regions) -> rowptr/cursor/dinv ----------
__global__ void k_scan() {
    __shared__ int sm[1024];
    int tid = threadIdx.x;
    const int chunk = (NN + 1023) / 1024;
    int start = tid * chunk;
    int end = min(start + chunk, NN);
    int s = 0;
    for (int i = start; i < end; i++) s += (g_degcnt[i] + 7) & ~7;
    sm[tid] = s;
    __syncthreads();
    for (int off = 1; off < 1024; off <<= 1) {
        int v = 0;
        if (tid >= off) v = sm[tid - off];
        __syncthreads();
        sm[tid] += v;
        __syncthreads();
    }
    int run = sm[tid] - s;
    for (int i = start; i < end; i++) {
        int d = g_degcnt[i];
        g_rowptr[i] = run;
        g_cursor[i] = run;
        g_dinv[i] = rsqrtf((float)(d + 1));
        run += (d + 7) & ~7;
    }
    if (tid == 1023) g_rowptr[NN] = sm[1023];
}

// ---------- 4. counting-sort edges by dst ----------
__global__ void k_fill(const int* __restrict__ src, const int* __restrict__ dst) {
    int i = blockIdx.x * 256 + threadIdx.x;
    if (i < EE) {
        int d = dst[i];
        int pos = atomicAdd(&g_cursor[d], 1);
        g_colsrc[pos] = src[i];
    }
}

// ---------- 4b. convert x -> bf16 ----------
__global__ void k_prepx(const float* __restrict__ x) {
    int i = blockIdx.x * blockDim.x + threadIdx.x;
    int stride = gridDim.x * blockDim.x;
    const int total = NN * HH / 2;
    unsigned int* out = (unsigned int*)g_bufX;
    const float2* in = (const float2*)x;
    for (int j = i; j < total; j += stride) {
        float2 v = in[j];
        out[j] = f2bf(v.x, v.y);
    }
}

// ---------- 4c. transpose + split weights: Wt_hi/Wt_lo[n][k] ----------
__global__ void k_prepw(const float* __restrict__ W1, const float* __restrict__ W2,
                        const float* __restrict__ W3) {
    int i = blockIdx.x * 256 + threadIdx.x;
    if (i >= 3 * HH * HH) return;
    int w = i / (HH * HH);
    int j = i % (HH * HH);
    int n = j >> 7, k = j & 127;
    const float* Wp = (w == 0) ? W1 : (w == 1) ? W2 : W3;
    float v = Wp[k * HH + n];
    __nv_bfloat16 hi = __float2bfloat16(v);
    float lo = v - __bfloat162float(hi);
    g_whi[w][n * HH + k] = hi;
    g_wlo[w][n * HH + k] = __float2bfloat16(lo);
}

// ---------- 5. HMMA GEMM: out[r][c] = (sum_k A[r][k]*W[k][c]) * dinv[r] ----------
#define ROWB 272
#define SM_WH 34816
#define SM_WL 69632
#define GT_SMEM 104448
__global__ void __launch_bounds__(256) k_gemm_mma(const __nv_bfloat16* __restrict__ A,
                                                  const __nv_bfloat16* __restrict__ Whi,
                                                  const __nv_bfloat16* __restrict__ Wlo,
                                                  __nv_bfloat16* __restrict__ out) {
    extern __shared__ char smem[];
    const int tid = threadIdx.x;
    const int wid = tid >> 5;
    const int lane = tid & 31;
    const int rowBase = blockIdx.x * 128;

    // stage A (zero-filled OOB) + Whi + Wlo
    const uint4* Ag = (const uint4*)A;
    const uint4* Wh = (const uint4*)Whi;
    const uint4* Wl = (const uint4*)Wlo;
    const uint4 z4 = make_uint4(0u, 0u, 0u, 0u);
    for (int i = tid; i < 2048; i += 256) {
        int r = i >> 4, c = i & 15;
        int gr = rowBase + r;
        uint4 v = (gr < NN) ? Ag[(size_t)gr * 16 + c] : z4;
        *(uint4*)(smem + r * ROWB + c * 16) = v;
        *(uint4*)(smem + SM_WH + r * ROWB + c * 16) = Wh[i];
        *(uint4*)(smem + SM_WL + r * ROWB + c * 16) = Wl[i];
    }
    __syncthreads();

    unsigned int sb;
    asm("{ .reg .u64 t; cvta.to.shared.u64 t, %1; cvt.u32.u64 %0, t; }" : "=r"(sb) : "l"(smem));
    const int R = wid * 16;

    float acc[16][4];
#pragma unroll
    for (int nb = 0; nb < 16; nb++)
#pragma unroll
        for (int j = 0; j < 4; j++) acc[nb][j] = 0.f;

    unsigned int aBase = sb + (R + (lane & 15)) * ROWB + (lane >> 4) * 16;
    unsigned int bRow = (lane & 7) * ROWB + ((lane >> 3) & 1) * 16;
    unsigned int bhBase = sb + SM_WH + bRow;
    unsigned int blBase = sb + SM_WL + bRow;

#pragma unroll
    for (int ks = 0; ks < 8; ks++) {
        unsigned int a0, a1, a2, a3;
        asm volatile("ldmatrix.sync.aligned.m8n8.x4.shared.b16 {%0,%1,%2,%3}, [%4];"
                     : "=r"(a0), "=r"(a1), "=r"(a2), "=r"(a3)
                     : "r"(aBase + ks * 32));
#pragma unroll
        for (int nb = 0; nb < 16; nb++) {
            unsigned int b0, b1;
            asm volatile("ldmatrix.sync.aligned.m8n8.x2.shared.b16 {%0,%1}, [%2];"
                         : "=r"(b0), "=r"(b1)
                         : "r"(bhBase + nb * (8 * ROWB) + ks * 32));
            asm volatile("mma.sync.aligned.m16n8k16.row.col.f32.bf16.bf16.f32 "
                         "{%0,%1,%2,%3}, {%4,%5,%6,%7}, {%8,%9}, {%0,%1,%2,%3};"
                         : "+f"(acc[nb][0]), "+f"(acc[nb][1]), "+f"(acc[nb][2]), "+f"(acc[nb][3])
                         : "r"(a0), "r"(a1), "r"(a2), "r"(a3), "r"(b0), "r"(b1));
            asm volatile("ldmatrix.sync.aligned.m8n8.x2.shared.b16 {%0,%1}, [%2];"
                         : "=r"(b0), "=r"(b1)
                         : "r"(blBase + nb * (8 * ROWB) + ks * 32));
            asm volatile("mma.sync.aligned.m16n8k16.row.col.f32.bf16.bf16.f32 "
                         "{%0,%1,%2,%3}, {%4,%5,%6,%7}, {%8,%9}, {%0,%1,%2,%3};"
                         : "+f"(acc[nb][0]), "+f"(acc[nb][1]), "+f"(acc[nb][2]), "+f"(acc[nb][3])
                         : "r"(a0), "r"(a1), "r"(a2), "r"(a3), "r"(b0), "r"(b1));
        }
    }

    // epilogue: scale by dinv, repack via smem (reuse A region), coalesced STG.128
    __syncthreads();
    {
        int r0l = R + (lane >> 2);
        int r1l = r0l + 8;
        int gr0 = rowBase + r0l;
        int gr1 = rowBase + r1l;
        float d0 = (gr0 < NN) ? g_dinv[gr0] : 0.f;
        float d1 = (gr1 < NN) ? g_dinv[gr1] : 0.f;
        int cOff = (lane & 3) * 2;
#pragma unroll
        for (int nb = 0; nb < 16; nb++) {
            int c = nb * 8 + cOff;
            *(unsigned int*)(smem + r0l * ROWB + c * 2) = f2bf(acc[nb][0] * d0, acc[nb][1] * d0);
            *(unsigned int*)(smem + r1l * ROWB + c * 2) = f2bf(acc[nb][2] * d1, acc[nb][3] * d1);
        }
    }
    __syncthreads();
    for (int i = tid; i < 2048; i += 256) {
        int r = i >> 4, c = i & 15;
        int gr = rowBase + r;
        if (gr < NN)
            ((uint4*)out)[(size_t)gr * 16 + c] = *(uint4*)(smem + r * ROWB + c * 16);
    }
}

// ---------- 6. aggregation: 2 nodes per warp, 16B gathers, padded CSR (MLP=8 always) ----------
__global__ void __launch_bounds__(256) k_agg(const __nv_bfloat16* __restrict__ hs,
                                             const float* __restrict__ b,
                                             __nv_bfloat16* __restrict__ out) {
    int warp = (blockIdx.x * blockDim.x + threadIdx.x) >> 5;
    int lane = threadIdx.x & 31;
    int half = lane >> 4;        // 0 / 1
    int hl = lane & 15;          // chunk within row (16 x uint4 = 256B)
    int node = warp * 2 + half;
    if (node >= NN) return;

    const uint4* hs4 = (const uint4*)hs;

    // self-loop term
    uint4 sv = hs4[(size_t)node * 16 + hl];
    float2 t0 = bf2f(sv.x), t1 = bf2f(sv.y), t2 = bf2f(sv.z), t3 = bf2f(sv.w);
    float a0 = t0.x, a1 = t0.y, a2 = t1.x, a3 = t1.y;
    float a4 = t2.x, a5 = t2.y, a6 = t3.x, a7 = t3.y;

    int e = g_rowptr[node];
    int end = g_rowptr[node + 1];   // padded region, length % 8 == 0
    for (; e < end; e += 8) {
        int n0 = g_colsrc[e + 0], n1 = g_colsrc[e + 1];
        int n2 = g_colsrc[e + 2], n3 = g_colsrc[e + 3];
        int n4 = g_colsrc[e + 4], n5 = g_colsrc[e + 5];
        int n6 = g_colsrc[e + 6], n7 = g_colsrc[e + 7];
        uint4 v0 = hs4[(size_t)n0 * 16 + hl];
        uint4 v1 = hs4[(size_t)n1 * 16 + hl];
        uint4 v2 = hs4[(size_t)n2 * 16 + hl];
        uint4 v3 = hs4[(size_t)n3 * 16 + hl];
        uint4 v4 = hs4[(size_t)n4 * 16 + hl];
        uint4 v5 = hs4[(size_t)n5 * 16 + hl];
        uint4 v6 = hs4[(size_t)n6 * 16 + hl];
        uint4 v7 = hs4[(size_t)n7 * 16 + hl];
#define ACC8(V) { \
        float2 q0 = bf2f(V.x), q1 = bf2f(V.y), q2 = bf2f(V.z), q3 = bf2f(V.w); \
        a0 += q0.x; a1 += q0.y; a2 += q1.x; a3 += q1.y; \
        a4 += q2.x; a5 += q2.y; a6 += q3.x; a7 += q3.y; }
        ACC8(v0) ACC8(v1) ACC8(v2) ACC8(v3) ACC8(v4) ACC8(v5) ACC8(v6) ACC8(v7)
#undef ACC8
    }

    float di = g_dinv[node];
    float4 bb0 = ((const float4*)b)[hl * 2];
    float4 bb1 = ((const float4*)b)[hl * 2 + 1];
    uint4 st;
    st.x = f2bf(elu_f(a0 * di + bb0.x), elu_f(a1 * di + bb0.y));
    st.y = f2bf(elu_f(a2 * di + bb0.z), elu_f(a3 * di + bb0.w));
    st.z = f2bf(elu_f(a4 * di + bb1.x), elu_f(a5 * di + bb1.y));
    st.w = f2bf(elu_f(a6 * di + bb1.z), elu_f(a7 * di + bb1.w));
    ((uint4*)out)[(size_t)node * 16 + hl] = st;
}

// ---------- 7. mean-pool ----------
#define POOL_NPB 512
__global__ void k_pool(const __nv_bfloat16* __restrict__ act, const int* __restrict__ batch) {
    int col = threadIdx.x;
    int start = blockIdx.x * POOL_NPB;
    if (start >= NN) return;
    int end = min(start + POOL_NPB, NN);
    float acc = 0.f;
    int cur = batch[start];
    int cl = 0;
    for (int i = start; i < end; i++) {
        int bb = batch[i];
        if (bb != cur) {
            atomicAdd(&g_sums[cur * HH + col], acc);
            if (col == 0) atomicAdd(&g_cnt[cur], cl);
            acc = 0.f; cl = 0; cur = bb;
        }
        acc += __bfloat162float(act[(size_t)i * HH + col]);
        cl++;
    }
    atomicAdd(&g_sums[cur * HH + col], acc);
    if (col == 0) atomicAdd(&g_cnt[cur], cl);
}

// ---------- 8. classifier head ----------
__global__ void k_mlp(const float* __restrict__ Wc1, const float* __restrict__ bc1,
                      const float* __restrict__ Wc2, const float* __restrict__ bc2,
                      float* __restrict__ out) {
    __shared__ float gs[GG][129];
    int tid = threadIdx.x;
    for (int idx = tid; idx < GG * HH; idx += 256) {
        int g = idx >> 7, k = idx & 127;
        float c = fmaxf((float)g_cnt[g], 1.f);
        gs[g][k] = g_sums[idx] / c;
    }
    __syncthreads();
    int gid = tid >> 2;
    int q = tid & 3;
    float part = 0.f;
    for (int j = q * 16; j < q * 16 + 16; j++) {
        float z = bc1[j];
#pragma unroll 4
        for (int k = 0; k < 128; k++) z += gs[gid][k] * Wc1[k * 64 + j];
        part += fmaxf(z, 0.f) * Wc2[j];
    }
    part += __shfl_down_sync(0xffffffffu, part, 2);
    part += __shfl_down_sync(0xffffffffu, part, 1);
    if (q == 0) out[gid] = 1.f / (1.f + expf(-(part + bc2[0])));
}

// ---------- launch ----------
extern "C" void kernel_launch(void* const* d_in, const int* in_sizes, int n_in,
                              void* d_out, int out_size) {
    const float* x   = (const float*)d_in[0];
    const int*   ei  = (const int*)d_in[1];
    const int*   bat = (const int*)d_in[2];
    const float* W1  = (const float*)d_in[3];
    const float* b1  = (const float*)d_in[4];
    const float* W2  = (const float*)d_in[5];
    const float* b2  = (const float*)d_in[6];
    const float* W3  = (const float*)d_in[7];
    const float* b3  = (const float*)d_in[8];
    const float* Wc1 = (const float*)d_in[9];
    const float* bc1 = (const float*)d_in[10];
    const float* Wc2 = (const float*)d_in[11];
    const float* bc2 = (const float*)d_in[12];
    float* out = (float*)d_out;

    const int* src = ei;
    const int* dst = ei + EE;

    cudaFuncSetAttribute(k_gemm_mma, cudaFuncAttributeMaxDynamicSharedMemorySize, GT_SMEM);

    void *pA, *pB, *pX, *pWh, *pWl;
    cudaGetSymbolAddress(&pA, g_bufA);
    cudaGetSymbolAddress(&pB, g_bufB);
    cudaGetSymbolAddress(&pX, g_bufX);
    cudaGetSymbolAddress(&pWh, g_whi);
    cudaGetSymbolAddress(&pWl, g_wlo);
    __nv_bfloat16* bufA = (__nv_bfloat16*)pA;
    __nv_bfloat16* bufB = (__nv_bfloat16*)pB;
    __nv_bfloat16* bufX = (__nv_bfloat16*)pX;
    __nv_bfloat16* whi = (__nv_bfloat16*)pWh;
    __nv_bfloat16* wlo = (__nv_bfloat16*)pWl;

    k_init<<<1024, 256>>>();
    k_hist<<<(EE + 255) / 256, 256>>>(dst);
    k_scan<<<1, 1024>>>();
    k_fill<<<(EE + 255) / 256, 256>>>(src, dst);
    k_prepx<<<1024, 256>>>(x);
    k_prepw<<<192, 256>>>(W1, W2, W3);

    const int gemm_grid = (NN + 127) / 128;
    const int agg_grid  = (NN / 2 + 7) / 8;   // 2 nodes per warp, 8 warps per block

    k_gemm_mma<<<gemm_grid, 256, GT_SMEM>>>(bufX, whi, wlo, bufA);
    k_agg<<<agg_grid, 256>>>(bufA, b1, bufB);
    k_gemm_mma<<<gemm_grid, 256, GT_SMEM>>>(bufB, whi + HH * HH, wlo + HH * HH, bufA);
    k_agg<<<agg_grid, 256>>>(bufA, b2, bufB);
    k_gemm_mma<<<gemm_grid, 256, GT_SMEM>>>(bufB, whi + 2 * HH * HH, wlo + 2 * HH * HH, bufA);
    k_agg<<<agg_grid, 256>>>(bufA, b3, bufB);

    k_pool<<<(NN + POOL_NPB - 1) / POOL_NPB, 128>>>(bufB, bat);
    k_mlp<<<1, 256>>>(Wc1, bc1, Wc2, bc2, out);
}

// round 10
// speedup vs baseline: 1.4164x; 1.4164x over previous
#include <cuda_runtime.h>
#include <cuda_bf16.h>
#include <math.h>

#define NN 100000
#define EE 1600000
#define HH 128
#define GG 64
#define SCAN_BLKS 100
#define SCAN_NPB 1000

// ---------- device scratch ----------
__device__ int   g_degcnt[NN];
__device__ float g_dinv[NN];
__device__ int   g_rowptr[NN + 1];
__device__ int   g_cursor[NN];
__device__ int   g_colsrc[EE];
__device__ int   g_bsum[SCAN_BLKS];
__device__ __align__(16) __nv_bfloat16 g_bufA[(size_t)(NN + 1) * HH];  // +1 dummy zero row
__device__ __align__(16) __nv_bfloat16 g_bufB[(size_t)(NN + 1) * HH];  // +1 dummy zero row
__device__ __align__(16) __nv_bfloat16 g_whi[3][HH * HH];   // Wt_hi[n][k]
__device__ __align__(16) __nv_bfloat16 g_wlo[3][HH * HH];   // Wt_lo[n][k]
__device__ float g_sums[GG * HH];
__device__ int   g_cnt[GG];

// ---------- helpers ----------
__device__ __forceinline__ float2 bf2f(unsigned int v) {
    __nv_bfloat162 b = *reinterpret_cast<__nv_bfloat162*>(&v);
    return __bfloat1622float2(b);
}
__device__ __forceinline__ unsigned int f2bf(float a, float b) {
    __nv_bfloat162 r = __float22bfloat162_rn(make_float2(a, b));
    return *reinterpret_cast<unsigned int*>(&r);
}
__device__ __forceinline__ float elu_f(float x) { return x > 0.f ? x : expm1f(x); }

// ---------- 1. zero scratch + dummy rows ----------
__global__ void k_init() {
    int i = blockIdx.x * blockDim.x + threadIdx.x;
    int stride = gridDim.x * blockDim.x;
    for (int j = i; j < NN; j += stride) g_degcnt[j] = 0;
    for (int j = i; j < GG * HH; j += stride) g_sums[j] = 0.f;
    for (int j = i; j < GG; j += stride) g_cnt[j] = 0;
    for (int j = i; j < HH; j += stride) {
        g_bufA[(size_t)NN * HH + j] = __float2bfloat16(0.f);
        g_bufB[(size_t)NN * HH + j] = __float2bfloat16(0.f);
    }
}

// ---------- 2. in-degree histogram ----------
__global__ void k_hist(const int* __restrict__ dst) {
    int i = blockIdx.x * 256 + threadIdx.x;
    if (i < EE) atomicAdd(&g_degcnt[dst[i]], 1);
}

// ---------- 3. parallel scan: partials -> scan -> write ----------
__global__ void k_scan1() {
    __shared__ int sm[256];
    int blk = blockIdx.x, tid = threadIdx.x;
    int base = blk * SCAN_NPB;
    int s = 0;
    for (int i = tid; i < SCAN_NPB; i += 256) {
        int n = base + i;
        if (n < NN) s += g_degcnt[n];
    }
    sm[tid] = s;
    __syncthreads();
    for (int off = 128; off > 0; off >>= 1) {
        if (tid < off) sm[tid] += sm[tid + off];
        __syncthreads();
    }
    if (tid == 0) g_bsum[blk] = sm[0];
}

__global__ void k_scan2() {
    __shared__ int sm[SCAN_BLKS];
    int tid = threadIdx.x;   // 128 threads
    int v = (tid < SCAN_BLKS) ? g_bsum[tid] : 0;
    if (tid < SCAN_BLKS) sm[tid] = v;
    __syncthreads();
    if (tid == 0) {
        int run = 0;
        for (int i = 0; i < SCAN_BLKS; i++) {
            int d = sm[i];
            g_bsum[i] = run;
            run += d;
        }
        g_rowptr[NN] = run;
    }
}

__global__ void k_scan3() {
    __shared__ int sm[256];
    int blk = blockIdx.x, tid = threadIdx.x;
    int base = blk * SCAN_NPB;
    const int chunk = 4;   // 256*4 = 1024 >= 1000
    int start = base + tid * chunk;
    int s = 0;
#pragma unroll
    for (int j = 0; j < chunk; j++) {
        int n = start + j;
        if (n < base + SCAN_NPB && n < NN) s += g_degcnt[n];
    }
    sm[tid] = s;
    __syncthreads();
    for (int off = 1; off < 256; off <<= 1) {
        int v = 0;
        if (tid >= off) v = sm[tid - off];
        __syncthreads();
        sm[tid] += v;
        __syncthreads();
    }
    int run = g_bsum[blk] + sm[tid] - s;   // exclusive prefix for this thread
#pragma unroll
    for (int j = 0; j < chunk; j++) {
        int n = start + j;
        if (n < base + SCAN_NPB && n < NN) {
            int d = g_degcnt[n];
            g_rowptr[n] = run;
            g_cursor[n] = run;
            g_dinv[n] = rsqrtf((float)(d + 1));
            run += d;
        }
    }
}

// ---------- 4. counting-sort edges by dst ----------
__global__ void k_fill(const int* __restrict__ src, const int* __restrict__ dst) {
    int i = blockIdx.x * 256 + threadIdx.x;
    if (i < EE) {
        int d = dst[i];
        int pos = atomicAdd(&g_cursor[d], 1);
        g_colsrc[pos] = src[i];
    }
}

// ---------- 4c. transpose + split weights: Wt_hi/Wt_lo[n][k] ----------
__global__ void k_prepw(const float* __restrict__ W1, const float* __restrict__ W2,
                        const float* __restrict__ W3) {
    int i = blockIdx.x * 256 + threadIdx.x;
    if (i >= 3 * HH * HH) return;
    int w = i / (HH * HH);
    int j = i % (HH * HH);
    int n = j >> 7, k = j & 127;
    const float* Wp = (w == 0) ? W1 : (w == 1) ? W2 : W3;
    float v = Wp[k * HH + n];
    __nv_bfloat16 hi = __float2bfloat16(v);
    float lo = v - __bfloat162float(hi);
    g_whi[w][n * HH + k] = hi;
    g_wlo[w][n * HH + k] = __float2bfloat16(lo);
}

// ---------- 5. HMMA GEMM mainloop (shared by both variants) ----------
#define ROWB 272
#define SM_WH 34816
#define SM_WL 69632
#define GT_SMEM 104448

#define GEMM_BODY(OUTSTORE)                                                            \
    unsigned int sb;                                                                   \
    asm("{ .reg .u64 t; cvta.to.shared.u64 t, %1; cvt.u32.u64 %0, t; }"                \
        : "=r"(sb) : "l"(smem));                                                       \
    const int R = wid * 16;                                                            \
    float acc[16][4];                                                                  \
    _Pragma("unroll") for (int nb = 0; nb < 16; nb++)                                  \
        _Pragma("unroll") for (int j = 0; j < 4; j++) acc[nb][j] = 0.f;                \
    unsigned int aBase = sb + (R + (lane & 15)) * ROWB + (lane >> 4) * 16;             \
    unsigned int bRow = (lane & 7) * ROWB + ((lane >> 3) & 1) * 16;                    \
    unsigned int bhBase = sb + SM_WH + bRow;                                           \
    unsigned int blBase = sb + SM_WL + bRow;                                           \
    _Pragma("unroll") for (int ks = 0; ks < 8; ks++) {                                 \
        unsigned int a0, a1, a2, a3;                                                   \
        asm volatile("ldmatrix.sync.aligned.m8n8.x4.shared.b16 {%0,%1,%2,%3}, [%4];"   \
                     : "=r"(a0), "=r"(a1), "=r"(a2), "=r"(a3)                          \
                     : "r"(aBase + ks * 32));                                          \
        _Pragma("unroll") for (int nb = 0; nb < 16; nb++) {                            \
            unsigned int b0, b1;                                                       \
            asm volatile("ldmatrix.sync.aligned.m8n8.x2.shared.b16 {%0,%1}, [%2];"     \
                         : "=r"(b0), "=r"(b1)                                          \
                         : "r"(bhBase + nb * (8 * ROWB) + ks * 32));                   \
            asm volatile("mma.sync.aligned.m16n8k16.row.col.f32.bf16.bf16.f32 "        \
                         "{%0,%1,%2,%3}, {%4,%5,%6,%7}, {%8,%9}, {%0,%1,%2,%3};"       \
                         : "+f"(acc[nb][0]), "+f"(acc[nb][1]),                         \
                           "+f"(acc[nb][2]), "+f"(acc[nb][3])                          \
                         : "r"(a0), "r"(a1), "r"(a2), "r"(a3), "r"(b0), "r"(b1));      \
            asm volatile("ldmatrix.sync.aligned.m8n8.x2.shared.b16 {%0,%1}, [%2];"     \
                         : "=r"(b0), "=r"(b1)                                          \
                         : "r"(blBase + nb * (8 * ROWB) + ks * 32));                   \
            asm volatile("mma.sync.aligned.m16n8k16.row.col.f32.bf16.bf16.f32 "        \
                         "{%0,%1,%2,%3}, {%4,%5,%6,%7}, {%8,%9}, {%0,%1,%2,%3};"       \
                         : "+f"(acc[nb][0]), "+f"(acc[nb][1]),                         \
                           "+f"(acc[nb][2]), "+f"(acc[nb][3])                          \
                         : "r"(a0), "r"(a1), "r"(a2), "r"(a3), "r"(b0), "r"(b1));      \
        }                                                                              \
    }                                                                                  \
    OUTSTORE

#define GEMM_EPILOGUE                                                                  \
    int r0 = rowBase + R + (lane >> 2);                                                \
    int r1 = r0 + 8;                                                                   \
    float d0 = (r0 < NN) ? g_dinv[r0] : 0.f;                                           \
    float d1 = (r1 < NN) ? g_dinv[r1] : 0.f;                                           \
    unsigned int colHalf = (lane & 3) * 2;                                             \
    _Pragma("unroll") for (int nb = 0; nb < 16; nb++) {                                \
        unsigned int c = nb * 8 + colHalf;                                             \
        if (r0 < NN)                                                                   \
            *(unsigned int*)&out[(size_t)r0 * HH + c] =                                \
                f2bf(acc[nb][0] * d0, acc[nb][1] * d0);                                \
        if (r1 < NN)                                                                   \
            *(unsigned int*)&out[(size_t)r1 * HH + c] =                                \
                f2bf(acc[nb][2] * d1, acc[nb][3] * d1);                                \
    }

// layer-1 variant: reads fp32 x directly, converts to bf16 while staging
__global__ void __launch_bounds__(256) k_gemm_x(const float* __restrict__ X,
                                                const __nv_bfloat16* __restrict__ Whi,
                                                const __nv_bfloat16* __restrict__ Wlo,
                                                __nv_bfloat16* __restrict__ out) {
    extern __shared__ char smem[];
    const int tid = threadIdx.x;
    const int wid = tid >> 5;
    const int lane = tid & 31;
    const int rowBase = blockIdx.x * 128;

    const float4* Xg = (const float4*)X;
    const uint4* Wh = (const uint4*)Whi;
    const uint4* Wl = (const uint4*)Wlo;
    for (int i = tid; i < 2048; i += 256) {
        int r = i >> 4, c = i & 15;
        int gr = rowBase + r;
        float4 u = make_float4(0.f, 0.f, 0.f, 0.f), v = u;
        if (gr < NN) {
            u = Xg[(size_t)gr * 32 + c * 2];
            v = Xg[(size_t)gr * 32 + c * 2 + 1];
        }
        uint4 st;
        st.x = f2bf(u.x, u.y); st.y = f2bf(u.z, u.w);
        st.z = f2bf(v.x, v.y); st.w = f2bf(v.z, v.w);
        *(uint4*)(smem + r * ROWB + c * 16) = st;
        *(uint4*)(smem + SM_WH + r * ROWB + c * 16) = Wh[i];
        *(uint4*)(smem + SM_WL + r * ROWB + c * 16) = Wl[i];
    }
    __syncthreads();
    GEMM_BODY(GEMM_EPILOGUE)
}

// layers 2/3 variant: bf16 activations
__global__ void __launch_bounds__(256) k_gemm_mma(const __nv_bfloat16* __restrict__ A,
                                                  const __nv_bfloat16* __restrict__ Whi,
                                                  const __nv_bfloat16* __restrict__ Wlo,
                                                  __nv_bfloat16* __restrict__ out) {
    extern __shared__ char smem[];
    const int tid = threadIdx.x;
    const int wid = tid >> 5;
    const int lane = tid & 31;
    const int rowBase = blockIdx.x * 128;

    const uint4* Ag = (const uint4*)A;
    const uint4* Wh = (const uint4*)Whi;
    const uint4* Wl = (const uint4*)Wlo;
    const uint4 z4 = make_uint4(0u, 0u, 0u, 0u);
    for (int i = tid; i < 2048; i += 256) {
        int r = i >> 4, c = i & 15;
        int gr = rowBase + r;
        uint4 v = (gr < NN) ? Ag[(size_t)gr * 16 + c] : z4;
        *(uint4*)(smem + r * ROWB + c * 16) = v;
        *(uint4*)(smem + SM_WH + r * ROWB + c * 16) = Wh[i];
        *(uint4*)(smem + SM_WL + r * ROWB + c * 16) = Wl[i];
    }
    __syncthreads();
    GEMM_BODY(GEMM_EPILOGUE)
}

// ---------- 6. aggregation: 1 node/warp, uint2 gathers, MLP=8 + masked-dummy tail ----------
__global__ void __launch_bounds__(256) k_agg(const __nv_bfloat16* __restrict__ hs,
                                             const float* __restrict__ b,
                                             __nv_bfloat16* __restrict__ out) {
    int warp = (blockIdx.x * blockDim.x + threadIdx.x) >> 5;
    int lane = threadIdx.x & 31;
    if (warp >= NN) return;
    const uint2* hs2 = (const uint2*)hs;

    uint2 sv = hs2[(size_t)warp * 32 + lane];
    float2 s0 = bf2f(sv.x), s1 = bf2f(sv.y);
    float4 acc = make_float4(s0.x, s0.y, s1.x, s1.y);

    int e = g_rowptr[warp];
    int end = g_rowptr[warp + 1];

#define GATHER8(I0, I1, I2, I3, I4, I5, I6, I7) {                              \
        uint2 v0 = hs2[(size_t)(I0) * 32 + lane];                              \
        uint2 v1 = hs2[(size_t)(I1) * 32 + lane];                              \
        uint2 v2 = hs2[(size_t)(I2) * 32 + lane];                              \
        uint2 v3 = hs2[(size_t)(I3) * 32 + lane];                              \
        uint2 v4 = hs2[(size_t)(I4) * 32 + lane];                              \
        uint2 v5 = hs2[(size_t)(I5) * 32 + lane];                              \
        uint2 v6 = hs2[(size_t)(I6) * 32 + lane];                              \
        uint2 v7 = hs2[(size_t)(I7) * 32 + lane];                              \
        float2 a0 = bf2f(v0.x), c0 = bf2f(v0.y);                               \
        float2 a1 = bf2f(v1.x), c1 = bf2f(v1.y);                               \
        float2 a2 = bf2f(v2.x), c2 = bf2f(v2.y);                               \
        float2 a3 = bf2f(v3.x), c3 = bf2f(v3.y);                               \
        float2 a4 = bf2f(v4.x), c4 = bf2f(v4.y);                               \
        float2 a5 = bf2f(v5.x), c5 = bf2f(v5.y);                               \
        float2 a6 = bf2f(v6.x), c6 = bf2f(v6.y);                               \
        float2 a7 = bf2f(v7.x), c7 = bf2f(v7.y);                               \
        acc.x += ((a0.x + a1.x) + (a2.x + a3.x)) + ((a4.x + a5.x) + (a6.x + a7.x)); \
        acc.y += ((a0.y + a1.y) + (a2.y + a3.y)) + ((a4.y + a5.y) + (a6.y + a7.y)); \
        acc.z += ((c0.x + c1.x) + (c2.x + c3.x)) + ((c4.x + c5.x) + (c6.x + c7.x)); \
        acc.w += ((c0.y + c1.y) + (c2.y + c3.y)) + ((c4.y + c5.y) + (c6.y + c7.y)); \
    }

    for (; e + 8 <= end; e += 8) {
        int n0 = g_colsrc[e + 0], n1 = g_colsrc[e + 1];
        int n2 = g_colsrc[e + 2], n3 = g_colsrc[e + 3];
        int n4 = g_colsrc[e + 4], n5 = g_colsrc[e + 5];
        int n6 = g_colsrc[e + 6], n7 = g_colsrc[e + 7];
        GATHER8(n0, n1, n2, n3, n4, n5, n6, n7)
    }
    if (e < end) {   // masked tail: out-of-range lanes hit the zeroed dummy row NN
        int n0 = (e + 0 < end) ? g_colsrc[e + 0] : NN;
        int n1 = (e + 1 < end) ? g_colsrc[e + 1] : NN;
        int n2 = (e + 2 < end) ? g_colsrc[e + 2] : NN;
        int n3 = (e + 3 < end) ? g_colsrc[e + 3] : NN;
        int n4 = (e + 4 < end) ? g_colsrc[e + 4] : NN;
        int n5 = (e + 5 < end) ? g_colsrc[e + 5] : NN;
        int n6 = (e + 6 < end) ? g_colsrc[e + 6] : NN;
        int n7 = (e + 7 < end) ? g_colsrc[e + 7] : NN;
        GATHER8(n0, n1, n2, n3, n4, n5, n6, n7)
    }
#undef GATHER8

    float di = g_dinv[warp];
    float4 bb = ((const float4*)b)[lane];
    uint2 st;
    st.x = f2bf(elu_f(acc.x * di + bb.x), elu_f(acc.y * di + bb.y));
    st.y = f2bf(elu_f(acc.z * di + bb.z), elu_f(acc.w * di + bb.w));
    ((uint2*)out)[(size_t)warp * 32 + lane] = st;
}

// ---------- 7. mean-pool ----------
#define POOL_NPB 512
__global__ void k_pool(const __nv_bfloat16* __restrict__ act, const int* __restrict__ batch) {
    int col = threadIdx.x;
    int start = blockIdx.x * POOL_NPB;
    if (start >= NN) return;
    int end = min(start + POOL_NPB, NN);
    float acc = 0.f;
    int cur = batch[start];
    int cl = 0;
    for (int i = start; i < end; i++) {
        int bb = batch[i];
        if (bb != cur) {
            atomicAdd(&g_sums[cur * HH + col], acc);
            if (col == 0) atomicAdd(&g_cnt[cur], cl);
            acc = 0.f; cl = 0; cur = bb;
        }
        acc += __bfloat162float(act[(size_t)i * HH + col]);
        cl++;
    }
    atomicAdd(&g_sums[cur * HH + col], acc);
    if (col == 0) atomicAdd(&g_cnt[cur], cl);
}

// ---------- 8. classifier head ----------
__global__ void k_mlp(const float* __restrict__ Wc1, const float* __restrict__ bc1,
                      const float* __restrict__ Wc2, const float* __restrict__ bc2,
                      float* __restrict__ out) {
    __shared__ float gs[GG][129];
    int tid = threadIdx.x;
    for (int idx = tid; idx < GG * HH; idx += 256) {
        int g = idx >> 7, k = idx & 127;
        float c = fmaxf((float)g_cnt[g], 1.f);
        gs[g][k] = g_sums[idx] / c;
    }
    __syncthreads();
    int gid = tid >> 2;
    int q = tid & 3;
    float part = 0.f;
    for (int j = q * 16; j < q * 16 + 16; j++) {
        float z = bc1[j];
#pragma unroll 4
        for (int k = 0; k < 128; k++) z += gs[gid][k] * Wc1[k * 64 + j];
        part += fmaxf(z, 0.f) * Wc2[j];
    }
    part += __shfl_down_sync(0xffffffffu, part, 2);
    part += __shfl_down_sync(0xffffffffu, part, 1);
    if (q == 0) out[gid] = 1.f / (1.f + expf(-(part + bc2[0])));
}

// ---------- launch ----------
extern "C" void kernel_launch(void* const* d_in, const int* in_sizes, int n_in,
                              void* d_out, int out_size) {
    const float* x   = (const float*)d_in[0];
    const int*   ei  = (const int*)d_in[1];
    const int*   bat = (const int*)d_in[2];
    const float* W1  = (const float*)d_in[3];
    const float* b1  = (const float*)d_in[4];
    const float* W2  = (const float*)d_in[5];
    const float* b2  = (const float*)d_in[6];
    const float* W3  = (const float*)d_in[7];
    const float* b3  = (const float*)d_in[8];
    const float* Wc1 = (const float*)d_in[9];
    const float* bc1 = (const float*)d_in[10];
    const float* Wc2 = (const float*)d_in[11];
    const float* bc2 = (const float*)d_in[12];
    float* out = (float*)d_out;

    const int* src = ei;
    const int* dst = ei + EE;

    cudaFuncSetAttribute(k_gemm_x, cudaFuncAttributeMaxDynamicSharedMemorySize, GT_SMEM);
    cudaFuncSetAttribute(k_gemm_mma, cudaFuncAttributeMaxDynamicSharedMemorySize, GT_SMEM);

    void *pA, *pB, *pWh, *pWl;
    cudaGetSymbolAddress(&pA, g_bufA);
    cudaGetSymbolAddress(&pB, g_bufB);
    cudaGetSymbolAddress(&pWh, g_whi);
    cudaGetSymbolAddress(&pWl, g_wlo);
    __nv_bfloat16* bufA = (__nv_bfloat16*)pA;
    __nv_bfloat16* bufB = (__nv_bfloat16*)pB;
    __nv_bfloat16* whi = (__nv_bfloat16*)pWh;
    __nv_bfloat16* wlo = (__nv_bfloat16*)pWl;

    k_init<<<256, 256>>>();
    k_hist<<<(EE + 255) / 256, 256>>>(dst);
    k_scan1<<<SCAN_BLKS, 256>>>();
    k_scan2<<<1, 128>>>();
    k_scan3<<<SCAN_BLKS, 256>>>();
    k_fill<<<(EE + 255) / 256, 256>>>(src, dst);
    k_prepw<<<192, 256>>>(W1, W2, W3);

    const int gemm_grid = (NN + 127) / 128;
    const int agg_grid  = (NN + 7) / 8;

    k_gemm_x  <<<gemm_grid, 256, GT_SMEM>>>(x, whi, wlo, bufA);
    k_agg<<<agg_grid, 256>>>(bufA, b1, bufB);
    k_gemm_mma<<<gemm_grid, 256, GT_SMEM>>>(bufB, whi + HH * HH, wlo + HH * HH, bufA);
    k_agg<<<agg_grid, 256>>>(bufA, b2, bufB);
    k_gemm_mma<<<gemm_grid, 256, GT_SMEM>>>(bufB, whi + 2 * HH * HH, wlo + 2 * HH * HH, bufA);
    k_agg<<<agg_grid, 256>>>(bufA, b3, bufB);

    k_pool<<<(NN + POOL_NPB - 1) / POOL_NPB, 128>>>(bufB, bat);
    k_mlp<<<1, 256>>>(Wc1, bc1, Wc2, bc2, out);
}

// round 15
// speedup vs baseline: 1.4965x; 1.0565x over previous
#include <cuda_runtime.h>
#include <cuda_bf16.h>
#include <math.h>

#define NN 100000
#define EE 1600000
#define HH 128
#define GG 64
#define SCAN_BLKS 100
#define SCAN_NPB 1000

// ---------- device scratch ----------
__device__ int   g_degcnt[NN];
__device__ float g_dinv[NN];
__device__ int   g_rowptr[NN + 1];
__device__ int   g_cursor[NN];
__device__ int   g_colsrc[EE];
__device__ int   g_bsum[SCAN_BLKS];
__device__ __align__(16) __nv_bfloat16 g_bufA[(size_t)(NN + 1) * HH];  // +1 dummy zero row
__device__ __align__(16) __nv_bfloat16 g_bufB[(size_t)(NN + 1) * HH];
__device__ __align__(16) __nv_bfloat16 g_whi[3][HH * HH];   // Wt[n][k] bf16
__device__ float g_sums[GG * HH];
__device__ int   g_cnt[GG];

// ---------- helpers ----------
__device__ __forceinline__ float2 bf2f(unsigned int v) {
    __nv_bfloat162 b = *reinterpret_cast<__nv_bfloat162*>(&v);
    return __bfloat1622float2(b);
}
__device__ __forceinline__ unsigned int f2bf(float a, float b) {
    __nv_bfloat162 r = __float22bfloat162_rn(make_float2(a, b));
    return *reinterpret_cast<unsigned int*>(&r);
}
__device__ __forceinline__ float elu_f(float x) { return x > 0.f ? x : expm1f(x); }

// ---------- CSR chain (stream 2) ----------
__global__ void k_zdeg() {
    int i = blockIdx.x * blockDim.x + threadIdx.x;
    if (i < NN) g_degcnt[i] = 0;
}

__global__ void k_hist(const int* __restrict__ dst) {
    int i = blockIdx.x * 256 + threadIdx.x;
    if (i < EE) atomicAdd(&g_degcnt[dst[i]], 1);
}

__global__ void k_scan1() {
    __shared__ int sm[256];
    int blk = blockIdx.x, tid = threadIdx.x;
    int base = blk * SCAN_NPB;
    int s = 0;
    for (int i = tid; i < SCAN_NPB; i += 256) {
        int n = base + i;
        if (n < NN) s += g_degcnt[n];
    }
    sm[tid] = s;
    __syncthreads();
    for (int off = 128; off > 0; off >>= 1) {
        if (tid < off) sm[tid] += sm[tid + off];
        __syncthreads();
    }
    if (tid == 0) g_bsum[blk] = sm[0];
}

// scan3 with inline scan of block sums (merged old scan2)
__global__ void k_scan3() {
    __shared__ int sm[256];
    __shared__ int sbase;
    int blk = blockIdx.x, tid = threadIdx.x;
    int base = blk * SCAN_NPB;

    if (tid == 0) {
        int run = 0;
        for (int i = 0; i < blk; i++) run += g_bsum[i];
        sbase = run;
    }

    const int chunk = 4;   // 256*4 = 1024 >= 1000
    int start = base + tid * chunk;
    int s = 0;
#pragma unroll
    for (int j = 0; j < chunk; j++) {
        int n = start + j;
        if (n < base + SCAN_NPB && n < NN) s += g_degcnt[n];
    }
    sm[tid] = s;
    __syncthreads();
    for (int off = 1; off < 256; off <<= 1) {
        int v = 0;
        if (tid >= off) v = sm[tid - off];
        __syncthreads();
        sm[tid] += v;
        __syncthreads();
    }
    int run = sbase + sm[tid] - s;   // exclusive prefix
#pragma unroll
    for (int j = 0; j < chunk; j++) {
        int n = start + j;
        if (n < base + SCAN_NPB && n < NN) {
            int d = g_degcnt[n];
            g_rowptr[n] = run;
            g_cursor[n] = run;
            g_dinv[n] = rsqrtf((float)(d + 1));
            run += d;
        }
    }
    if (blk == SCAN_BLKS - 1 && tid == 255) g_rowptr[NN] = sbase + sm[255];
}

__global__ void k_fill(const int* __restrict__ src, const int* __restrict__ dst) {
    int i = blockIdx.x * 256 + threadIdx.x;
    if (i < EE) {
        int d = dst[i];
        int pos = atomicAdd(&g_cursor[d], 1);
        g_colsrc[pos] = src[i];
    }
}

// ---------- feature chain (main stream) ----------
__global__ void k_init_misc() {
    int i = blockIdx.x * blockDim.x + threadIdx.x;
    int stride = gridDim.x * blockDim.x;
    for (int j = i; j < GG * HH; j += stride) g_sums[j] = 0.f;
    for (int j = i; j < GG; j += stride) g_cnt[j] = 0;
    for (int j = i; j < HH; j += stride) {
        g_bufA[(size_t)NN * HH + j] = __float2bfloat16(0.f);
        g_bufB[(size_t)NN * HH + j] = __float2bfloat16(0.f);
    }
}

__global__ void k_prepw(const float* __restrict__ W1, const float* __restrict__ W2,
                        const float* __restrict__ W3) {
    int i = blockIdx.x * 256 + threadIdx.x;
    if (i >= 3 * HH * HH) return;
    int w = i / (HH * HH);
    int j = i % (HH * HH);
    int n = j >> 7, k = j & 127;
    const float* Wp = (w == 0) ? W1 : (w == 1) ? W2 : W3;
    g_whi[w][n * HH + k] = __float2bfloat16(Wp[k * HH + n]);
}

// ---------- HMMA GEMM (single bf16 W) ----------
#define ROWB 272
#define SM_WH 34816
#define GT_SMEM 69632

#define GEMM_BODY                                                                      \
    unsigned int sb;                                                                   \
    asm("{ .reg .u64 t; cvta.to.shared.u64 t, %1; cvt.u32.u64 %0, t; }"                \
        : "=r"(sb) : "l"(smem));                                                       \
    const int R = wid * 16;                                                            \
    float acc[16][4];                                                                  \
    _Pragma("unroll") for (int nb = 0; nb < 16; nb++)                                  \
        _Pragma("unroll") for (int j = 0; j < 4; j++) acc[nb][j] = 0.f;                \
    unsigned int aBase = sb + (R + (lane & 15)) * ROWB + (lane >> 4) * 16;             \
    unsigned int bRow = (lane & 7) * ROWB + ((lane >> 3) & 1) * 16;                    \
    unsigned int bhBase = sb + SM_WH + bRow;                                           \
    _Pragma("unroll") for (int ks = 0; ks < 8; ks++) {                                 \
        unsigned int a0, a1, a2, a3;                                                   \
        asm volatile("ldmatrix.sync.aligned.m8n8.x4.shared.b16 {%0,%1,%2,%3}, [%4];"   \
                     : "=r"(a0), "=r"(a1), "=r"(a2), "=r"(a3)                          \
                     : "r"(aBase + ks * 32));                                          \
        _Pragma("unroll") for (int nb = 0; nb < 16; nb++) {                            \
            unsigned int b0, b1;                                                       \
            asm volatile("ldmatrix.sync.aligned.m8n8.x2.shared.b16 {%0,%1}, [%2];"     \
                         : "=r"(b0), "=r"(b1)                                          \
                         : "r"(bhBase + nb * (8 * ROWB) + ks * 32));                   \
            asm volatile("mma.sync.aligned.m16n8k16.row.col.f32.bf16.bf16.f32 "        \
                         "{%0,%1,%2,%3}, {%4,%5,%6,%7}, {%8,%9}, {%0,%1,%2,%3};"       \
                         : "+f"(acc[nb][0]), "+f"(acc[nb][1]),                         \
                           "+f"(acc[nb][2]), "+f"(acc[nb][3])                          \
                         : "r"(a0), "r"(a1), "r"(a2), "r"(a3), "r"(b0), "r"(b1));      \
        }                                                                              \
    }                                                                                  \
    int r0 = rowBase + R + (lane >> 2);                                                \
    int r1 = r0 + 8;                                                                   \
    float d0 = (r0 < NN) ? g_dinv[r0] : 0.f;                                           \
    float d1 = (r1 < NN) ? g_dinv[r1] : 0.f;                                           \
    unsigned int colHalf = (lane & 3) * 2;                                             \
    _Pragma("unroll") for (int nb = 0; nb < 16; nb++) {                                \
        unsigned int c = nb * 8 + colHalf;                                             \
        if (r0 < NN)                                                                   \
            *(unsigned int*)&out[(size_t)r0 * HH + c] =                                \
                f2bf(acc[nb][0] * d0, acc[nb][1] * d0);                                \
        if (r1 < NN)                                                                   \
            *(unsigned int*)&out[(size_t)r1 * HH + c] =                                \
                f2bf(acc[nb][2] * d1, acc[nb][3] * d1);                                \
    }

// layer-1: reads fp32 x, converts while staging
__global__ void __launch_bounds__(256) k_gemm_x(const float* __restrict__ X,
                                                const __nv_bfloat16* __restrict__ Whi,
                                                __nv_bfloat16* __restrict__ out) {
    extern __shared__ char smem[];
    const int tid = threadIdx.x;
    const int wid = tid >> 5;
    const int lane = tid & 31;
    const int rowBase = blockIdx.x * 128;

    const float4* Xg = (const float4*)X;
    const uint4* Wh = (const uint4*)Whi;
    for (int i = tid; i < 2048; i += 256) {
        int r = i >> 4, c = i & 15;
        int gr = rowBase + r;
        float4 u = make_float4(0.f, 0.f, 0.f, 0.f), v = u;
        if (gr < NN) {
            u = Xg[(size_t)gr * 32 + c * 2];
            v = Xg[(size_t)gr * 32 + c * 2 + 1];
        }
        uint4 st;
        st.x = f2bf(u.x, u.y); st.y = f2bf(u.z, u.w);
        st.z = f2bf(v.x, v.y); st.w = f2bf(v.z, v.w);
        *(uint4*)(smem + r * ROWB + c * 16) = st;
        *(uint4*)(smem + SM_WH + r * ROWB + c * 16) = Wh[i];
    }
    __syncthreads();
    GEMM_BODY
}

// layers 2/3: bf16 activations
__global__ void __launch_bounds__(256) k_gemm_mma(const __nv_bfloat16* __restrict__ A,
                                                  const __nv_bfloat16* __restrict__ Whi,
                                                  __nv_bfloat16* __restrict__ out) {
    extern __shared__ char smem[];
    const int tid = threadIdx.x;
    const int wid = tid >> 5;
    const int lane = tid & 31;
    const int rowBase = blockIdx.x * 128;

    const uint4* Ag = (const uint4*)A;
    const uint4* Wh = (const uint4*)Whi;
    const uint4 z4 = make_uint4(0u, 0u, 0u, 0u);
    for (int i = tid; i < 2048; i += 256) {
        int r = i >> 4, c = i & 15;
        int gr = rowBase + r;
        uint4 v = (gr < NN) ? Ag[(size_t)gr * 16 + c] : z4;
        *(uint4*)(smem + r * ROWB + c * 16) = v;
        *(uint4*)(smem + SM_WH + r * ROWB + c * 16) = Wh[i];
    }
    __syncthreads();
    GEMM_BODY
}

// ---------- aggregation: 1 node/warp, uint2 gathers, MLP=8 + masked-dummy tail ----------
__global__ void __launch_bounds__(256) k_agg(const __nv_bfloat16* __restrict__ hs,
                                             const float* __restrict__ b,
                                             __nv_bfloat16* __restrict__ out) {
    int warp = (blockIdx.x * blockDim.x + threadIdx.x) >> 5;
    int lane = threadIdx.x & 31;
    if (warp >= NN) return;
    const uint2* hs2 = (const uint2*)hs;

    uint2 sv = hs2[(size_t)warp * 32 + lane];
    float2 s0 = bf2f(sv.x), s1 = bf2f(sv.y);
    float4 acc = make_float4(s0.x, s0.y, s1.x, s1.y);

    int e = g_rowptr[warp];
    int end = g_rowptr[warp + 1];

#define GATHER8(I0, I1, I2, I3, I4, I5, I6, I7) {                              \
        uint2 v0 = hs2[(size_t)(I0) * 32 + lane];                              \
        uint2 v1 = hs2[(size_t)(I1) * 32 + lane];                              \
        uint2 v2 = hs2[(size_t)(I2) * 32 + lane];                              \
        uint2 v3 = hs2[(size_t)(I3) * 32 + lane];                              \
        uint2 v4 = hs2[(size_t)(I4) * 32 + lane];                              \
        uint2 v5 = hs2[(size_t)(I5) * 32 + lane];                              \
        uint2 v6 = hs2[(size_t)(I6) * 32 + lane];                              \
        uint2 v7 = hs2[(size_t)(I7) * 32 + lane];                              \
        float2 a0 = bf2f(v0.x), c0 = bf2f(v0.y);                               \
        float2 a1 = bf2f(v1.x), c1 = bf2f(v1.y);                               \
        float2 a2 = bf2f(v2.x), c2 = bf2f(v2.y);                               \
        float2 a3 = bf2f(v3.x), c3 = bf2f(v3.y);                               \
        float2 a4 = bf2f(v4.x), c4 = bf2f(v4.y);                               \
        float2 a5 = bf2f(v5.x), c5 = bf2f(v5.y);                               \
        float2 a6 = bf2f(v6.x), c6 = bf2f(v6.y);                               \
        float2 a7 = bf2f(v7.x), c7 = bf2f(v7.y);                               \
        acc.x += ((a0.x + a1.x) + (a2.x + a3.x)) + ((a4.x + a5.x) + (a6.x + a7.x)); \
        acc.y += ((a0.y + a1.y) + (a2.y + a3.y)) + ((a4.y + a5.y) + (a6.y + a7.y)); \
        acc.z += ((c0.x + c1.x) + (c2.x + c3.x)) + ((c4.x + c5.x) + (c6.x + c7.x)); \
        acc.w += ((c0.y + c1.y) + (c2.y + c3.y)) + ((c4.y + c5.y) + (c6.y + c7.y)); \
    }

    for (; e + 8 <= end; e += 8) {
        int n0 = g_colsrc[e + 0], n1 = g_colsrc[e + 1];
        int n2 = g_colsrc[e + 2], n3 = g_colsrc[e + 3];
        int n4 = g_colsrc[e + 4], n5 = g_colsrc[e + 5];
        int n6 = g_colsrc[e + 6], n7 = g_colsrc[e + 7];
        GATHER8(n0, n1, n2, n3, n4, n5, n6, n7)
    }
    if (e < end) {   // masked tail: out-of-range lanes hit the zeroed dummy row NN
        int n0 = (e + 0 < end) ? g_colsrc[e + 0] : NN;
        int n1 = (e + 1 < end) ? g_colsrc[e + 1] : NN;
        int n2 = (e + 2 < end) ? g_colsrc[e + 2] : NN;
        int n3 = (e + 3 < end) ? g_colsrc[e + 3] : NN;
        int n4 = (e + 4 < end) ? g_colsrc[e + 4] : NN;
        int n5 = (e + 5 < end) ? g_colsrc[e + 5] : NN;
        int n6 = (e + 6 < end) ? g_colsrc[e + 6] : NN;
        int n7 = (e + 7 < end) ? g_colsrc[e + 7] : NN;
        GATHER8(n0, n1, n2, n3, n4, n5, n6, n7)
    }
#undef GATHER8

    float di = g_dinv[warp];
    float4 bb = ((const float4*)b)[lane];
    uint2 st;
    st.x = f2bf(elu_f(acc.x * di + bb.x), elu_f(acc.y * di + bb.y));
    st.y = f2bf(elu_f(acc.z * di + bb.z), elu_f(acc.w * di + bb.w));
    ((uint2*)out)[(size_t)warp * 32 + lane] = st;
}

// ---------- mean-pool ----------
#define POOL_NPB 512
__global__ void k_pool(const __nv_bfloat16* __restrict__ act, const int* __restrict__ batch) {
    int col = threadIdx.x;
    int start = blockIdx.x * POOL_NPB;
    if (start >= NN) return;
    int end = min(start + POOL_NPB, NN);
    float acc = 0.f;
    int cur = batch[start];
    int cl = 0;
    for (int i = start; i < end; i++) {
        int bb = batch[i];
        if (bb != cur) {
            atomicAdd(&g_sums[cur * HH + col], acc);
            if (col == 0) atomicAdd(&g_cnt[cur], cl);
            acc = 0.f; cl = 0; cur = bb;
        }
        acc += __bfloat162float(act[(size_t)i * HH + col]);
        cl++;
    }
    atomicAdd(&g_sums[cur * HH + col], acc);
    if (col == 0) atomicAdd(&g_cnt[cur], cl);
}

// ---------- classifier head ----------
__global__ void k_mlp(const float* __restrict__ Wc1, const float* __restrict__ bc1,
                      const float* __restrict__ Wc2, const float* __restrict__ bc2,
                      float* __restrict__ out) {
    __shared__ float gs[GG][129];
    int tid = threadIdx.x;
    for (int idx = tid; idx < GG * HH; idx += 256) {
        int g = idx >> 7, k = idx & 127;
        float c = fmaxf((float)g_cnt[g], 1.f);
        gs[g][k] = g_sums[idx] / c;
    }
    __syncthreads();
    int gid = tid >> 2;
    int q = tid & 3;
    float part = 0.f;
    for (int j = q * 16; j < q * 16 + 16; j++) {
        float z = bc1[j];
#pragma unroll 4
        for (int k = 0; k < 128; k++) z += gs[gid][k] * Wc1[k * 64 + j];
        part += fmaxf(z, 0.f) * Wc2[j];
    }
    part += __shfl_down_sync(0xffffffffu, part, 2);
    part += __shfl_down_sync(0xffffffffu, part, 1);
    if (q == 0) out[gid] = 1.f / (1.f + expf(-(part + bc2[0])));
}

// ---------- launch ----------
extern "C" void kernel_launch(void* const* d_in, const int* in_sizes, int n_in,
                              void* d_out, int out_size) {
    const float* x   = (const float*)d_in[0];
    const int*   ei  = (const int*)d_in[1];
    const int*   bat = (const int*)d_in[2];
    const float* W1  = (const float*)d_in[3];
    const float* b1  = (const float*)d_in[4];
    const float* W2  = (const float*)d_in[5];
    const float* b2  = (const float*)d_in[6];
    const float* W3  = (const float*)d_in[7];
    const float* b3  = (const float*)d_in[8];
    const float* Wc1 = (const float*)d_in[9];
    const float* bc1 = (const float*)d_in[10];
    const float* Wc2 = (const float*)d_in[11];
    const float* bc2 = (const float*)d_in[12];
    float* out = (float*)d_out;

    const int* src = ei;
    const int* dst = ei + EE;

    cudaFuncSetAttribute(k_gemm_x, cudaFuncAttributeMaxDynamicSharedMemorySize, GT_SMEM);
    cudaFuncSetAttribute(k_gemm_mma, cudaFuncAttributeMaxDynamicSharedMemorySize, GT_SMEM);

    void *pA, *pB, *pWh;
    cudaGetSymbolAddress(&pA, g_bufA);
    cudaGetSymbolAddress(&pB, g_bufB);
    cudaGetSymbolAddress(&pWh, g_whi);
    __nv_bfloat16* bufA = (__nv_bfloat16*)pA;
    __nv_bfloat16* bufB = (__nv_bfloat16*)pB;
    __nv_bfloat16* whi = (__nv_bfloat16*)pWh;

    // fork a second stream for the CSR chain (created/destroyed per call; capture-safe)
    cudaStream_t s2;
    cudaStreamCreateWithFlags(&s2, cudaStreamNonBlocking);
    cudaEvent_t evF, evJ;
    cudaEventCreateWithFlags(&evF, cudaEventDisableTiming);
    cudaEventCreateWithFlags(&evJ, cudaEventDisableTiming);

    cudaEventRecord(evF, 0);
    cudaStreamWaitEvent(s2, evF, 0);

    // stream 2: CSR build
    k_zdeg<<<(NN + 255) / 256, 256, 0, s2>>>();
    k_hist<<<(EE + 255) / 256, 256, 0, s2>>>(dst);
    k_scan1<<<SCAN_BLKS, 256, 0, s2>>>();
    k_scan3<<<SCAN_BLKS, 256, 0, s2>>>();
    k_fill<<<(EE + 255) / 256, 256, 0, s2>>>(src, dst);
    cudaEventRecord(evJ, s2);

    // main stream: feature path
    const int gemm_grid = (NN + 127) / 128;
    const int agg_grid  = (NN + 7) / 8;

    k_init_misc<<<64, 256>>>();
    k_prepw<<<192, 256>>>(W1, W2, W3);
    k_gemm_x<<<gemm_grid, 256, GT_SMEM>>>(x, whi, bufA);

    cudaStreamWaitEvent(0, evJ, 0);   // join: agg needs CSR + dinv

    k_agg<<<agg_grid, 256>>>(bufA, b1, bufB);
    k_gemm_mma<<<gemm_grid, 256, GT_SMEM>>>(bufB, whi + HH * HH, bufA);
    k_agg<<<agg_grid, 256>>>(bufA, b2, bufB);
    k_gemm_mma<<<gemm_grid, 256, GT_SMEM>>>(bufB, whi + 2 * HH * HH, bufA);
    k_agg<<<agg_grid, 256>>>(bufA, b3, bufB);

    k_pool<<<(NN + POOL_NPB - 1) / POOL_NPB, 128>>>(bufB, bat);
    k_mlp<<<1, 256>>>(Wc1, bc1, Wc2, bc2, out);

    cudaEventDestroy(evF);
    cudaEventDestroy(evJ);
    cudaStreamDestroy(s2);
}

// round 16
// speedup vs baseline: 1.5065x; 1.0067x over previous
#include <cuda_runtime.h>
#include <cuda_bf16.h>
#include <math.h>

#define NN 100000
#define EE 1600000
#define HH 128
#define GG 64
#define SCAN_BLKS 100
#define SCAN_NPB 1000

// ---------- device scratch ----------
__device__ int   g_degcnt[NN];
__device__ float g_dinv[NN];
__device__ int   g_rowptr[NN + 1];
__device__ int   g_cursor[NN];
__device__ int   g_colsrc[EE];
__device__ int   g_bsum[SCAN_BLKS];
__device__ __align__(16) __nv_bfloat16 g_bufA[(size_t)(NN + 1) * HH];  // +1 dummy zero row
__device__ __align__(16) __nv_bfloat16 g_bufB[(size_t)(NN + 1) * HH];
__device__ __align__(16) __nv_bfloat16 g_whi[3][HH * HH];   // Wt[n][k] bf16
__device__ float g_sums[GG * HH];
__device__ int   g_cnt[GG];

// ---------- helpers ----------
__device__ __forceinline__ float2 bf2f(unsigned int v) {
    __nv_bfloat162 b = *reinterpret_cast<__nv_bfloat162*>(&v);
    return __bfloat1622float2(b);
}
__device__ __forceinline__ unsigned int f2bf(float a, float b) {
    __nv_bfloat162 r = __float22bfloat162_rn(make_float2(a, b));
    return *reinterpret_cast<unsigned int*>(&r);
}
__device__ __forceinline__ float elu_f(float x) { return x > 0.f ? x : expm1f(x); }

// ---------- CSR chain (stream 2) ----------
__global__ void k_zdeg() {
    int i = blockIdx.x * blockDim.x + threadIdx.x;
    if (i < NN) g_degcnt[i] = 0;
}

__global__ void k_hist(const int* __restrict__ dst) {
    int i = blockIdx.x * 256 + threadIdx.x;
    if (i < EE) atomicAdd(&g_degcnt[dst[i]], 1);
}

__global__ void k_scan1() {
    __shared__ int sm[256];
    int blk = blockIdx.x, tid = threadIdx.x;
    int base = blk * SCAN_NPB;
    int s = 0;
    for (int i = tid; i < SCAN_NPB; i += 256) {
        int n = base + i;
        if (n < NN) s += g_degcnt[n];
    }
    sm[tid] = s;
    __syncthreads();
    for (int off = 128; off > 0; off >>= 1) {
        if (tid < off) sm[tid] += sm[tid + off];
        __syncthreads();
    }
    if (tid == 0) g_bsum[blk] = sm[0];
}

// scan3 with inline scan of block sums
__global__ void k_scan3() {
    __shared__ int sm[256];
    __shared__ int sbase;
    int blk = blockIdx.x, tid = threadIdx.x;
    int base = blk * SCAN_NPB;

    if (tid == 0) {
        int run = 0;
        for (int i = 0; i < blk; i++) run += g_bsum[i];
        sbase = run;
    }

    const int chunk = 4;
    int start = base + tid * chunk;
    int s = 0;
#pragma unroll
    for (int j = 0; j < chunk; j++) {
        int n = start + j;
        if (n < base + SCAN_NPB && n < NN) s += g_degcnt[n];
    }
    sm[tid] = s;
    __syncthreads();
    for (int off = 1; off < 256; off <<= 1) {
        int v = 0;
        if (tid >= off) v = sm[tid - off];
        __syncthreads();
        sm[tid] += v;
        __syncthreads();
    }
    int run = sbase + sm[tid] - s;
#pragma unroll
    for (int j = 0; j < chunk; j++) {
        int n = start + j;
        if (n < base + SCAN_NPB && n < NN) {
            int d = g_degcnt[n];
            g_rowptr[n] = run;
            g_cursor[n] = run;
            g_dinv[n] = rsqrtf((float)(d + 1));
            run += d;
        }
    }
    if (blk == SCAN_BLKS - 1 && tid == 255) g_rowptr[NN] = sbase + sm[255];
}

__global__ void k_fill(const int* __restrict__ src, const int* __restrict__ dst) {
    int i = blockIdx.x * 256 + threadIdx.x;
    if (i < EE) {
        int d = dst[i];
        int pos = atomicAdd(&g_cursor[d], 1);
        g_colsrc[pos] = src[i];
    }
}

// ---------- feature chain (main stream) ----------
__global__ void k_init_misc() {
    int i = blockIdx.x * blockDim.x + threadIdx.x;
    int stride = gridDim.x * blockDim.x;
    for (int j = i; j < GG * HH; j += stride) g_sums[j] = 0.f;
    for (int j = i; j < GG; j += stride) g_cnt[j] = 0;
    for (int j = i; j < HH; j += stride) {
        g_bufA[(size_t)NN * HH + j] = __float2bfloat16(0.f);
        g_bufB[(size_t)NN * HH + j] = __float2bfloat16(0.f);
    }
}

__global__ void k_prepw(const float* __restrict__ W1, const float* __restrict__ W2,
                        const float* __restrict__ W3) {
    int i = blockIdx.x * 256 + threadIdx.x;
    if (i >= 3 * HH * HH) return;
    int w = i / (HH * HH);
    int j = i % (HH * HH);
    int n = j >> 7, k = j & 127;
    const float* Wp = (w == 0) ? W1 : (w == 1) ? W2 : W3;
    g_whi[w][n * HH + k] = __float2bfloat16(Wp[k * HH + n]);
}

// ---------- HMMA GEMM (single bf16 W) ----------
#define ROWB 272
#define SM_WH 34816
#define GT_SMEM 69632

#define GEMM_BODY                                                                      \
    unsigned int sb;                                                                   \
    asm("{ .reg .u64 t; cvta.to.shared.u64 t, %1; cvt.u32.u64 %0, t; }"                \
        : "=r"(sb) : "l"(smem));                                                       \
    const int R = wid * 16;                                                            \
    float acc[16][4];                                                                  \
    _Pragma("unroll") for (int nb = 0; nb < 16; nb++)                                  \
        _Pragma("unroll") for (int j = 0; j < 4; j++) acc[nb][j] = 0.f;                \
    unsigned int aBase = sb + (R + (lane & 15)) * ROWB + (lane >> 4) * 16;             \
    unsigned int bRow = (lane & 7) * ROWB + ((lane >> 3) & 1) * 16;                    \
    unsigned int bhBase = sb + SM_WH + bRow;                                           \
    _Pragma("unroll") for (int ks = 0; ks < 8; ks++) {                                 \
        unsigned int a0, a1, a2, a3;                                                   \
        asm volatile("ldmatrix.sync.aligned.m8n8.x4.shared.b16 {%0,%1,%2,%3}, [%4];"   \
                     : "=r"(a0), "=r"(a1), "=r"(a2), "=r"(a3)                          \
                     : "r"(aBase + ks * 32));                                          \
        _Pragma("unroll") for (int nb = 0; nb < 16; nb++) {                            \
            unsigned int b0, b1;                                                       \
            asm volatile("ldmatrix.sync.aligned.m8n8.x2.shared.b16 {%0,%1}, [%2];"     \
                         : "=r"(b0), "=r"(b1)                                          \
                         : "r"(bhBase + nb * (8 * ROWB) + ks * 32));                   \
            asm volatile("mma.sync.aligned.m16n8k16.row.col.f32.bf16.bf16.f32 "        \
                         "{%0,%1,%2,%3}, {%4,%5,%6,%7}, {%8,%9}, {%0,%1,%2,%3};"       \
                         : "+f"(acc[nb][0]), "+f"(acc[nb][1]),                         \
                           "+f"(acc[nb][2]), "+f"(acc[nb][3])                          \
                         : "r"(a0), "r"(a1), "r"(a2), "r"(a3), "r"(b0), "r"(b1));      \
        }                                                                              \
    }                                                                                  \
    int r0 = rowBase + R + (lane >> 2);                                                \
    int r1 = r0 + 8;                                                                   \
    float d0 = (r0 < NN) ? g_dinv[r0] : 0.f;                                           \
    float d1 = (r1 < NN) ? g_dinv[r1] : 0.f;                                           \
    unsigned int colHalf = (lane & 3) * 2;                                             \
    _Pragma("unroll") for (int nb = 0; nb < 16; nb++) {                                \
        unsigned int c = nb * 8 + colHalf;                                             \
        if (r0 < NN)                                                                   \
            *(unsigned int*)&out[(size_t)r0 * HH + c] =                                \
                f2bf(acc[nb][0] * d0, acc[nb][1] * d0);                                \
        if (r1 < NN)                                                                   \
            *(unsigned int*)&out[(size_t)r1 * HH + c] =                                \
                f2bf(acc[nb][2] * d1, acc[nb][3] * d1);                                \
    }

// layer-1: reads fp32 x, converts while staging
__global__ void __launch_bounds__(256) k_gemm_x(const float* __restrict__ X,
                                                const __nv_bfloat16* __restrict__ Whi,
                                                __nv_bfloat16* __restrict__ out) {
    extern __shared__ char smem[];
    const int tid = threadIdx.x;
    const int wid = tid >> 5;
    const int lane = tid & 31;
    const int rowBase = blockIdx.x * 128;

    const float4* Xg = (const float4*)X;
    const uint4* Wh = (const uint4*)Whi;
    for (int i = tid; i < 2048; i += 256) {
        int r = i >> 4, c = i & 15;
        int gr = rowBase + r;
        float4 u = make_float4(0.f, 0.f, 0.f, 0.f), v = u;
        if (gr < NN) {
            u = Xg[(size_t)gr * 32 + c * 2];
            v = Xg[(size_t)gr * 32 + c * 2 + 1];
        }
        uint4 st;
        st.x = f2bf(u.x, u.y); st.y = f2bf(u.z, u.w);
        st.z = f2bf(v.x, v.y); st.w = f2bf(v.z, v.w);
        *(uint4*)(smem + r * ROWB + c * 16) = st;
        *(uint4*)(smem + SM_WH + r * ROWB + c * 16) = Wh[i];
    }
    __syncthreads();
    GEMM_BODY
}

// layers 2/3: bf16 activations
__global__ void __launch_bounds__(256) k_gemm_mma(const __nv_bfloat16* __restrict__ A,
                                                  const __nv_bfloat16* __restrict__ Whi,
                                                  __nv_bfloat16* __restrict__ out) {
    extern __shared__ char smem[];
    const int tid = threadIdx.x;
    const int wid = tid >> 5;
    const int lane = tid & 31;
    const int rowBase = blockIdx.x * 128;

    const uint4* Ag = (const uint4*)A;
    const uint4* Wh = (const uint4*)Whi;
    const uint4 z4 = make_uint4(0u, 0u, 0u, 0u);
    for (int i = tid; i < 2048; i += 256) {
        int r = i >> 4, c = i & 15;
        int gr = rowBase + r;
        uint4 v = (gr < NN) ? Ag[(size_t)gr * 16 + c] : z4;
        *(uint4*)(smem + r * ROWB + c * 16) = v;
        *(uint4*)(smem + SM_WH + r * ROWB + c * 16) = Wh[i];
    }
    __syncthreads();
    GEMM_BODY
}

// ---------- aggregation: 1 node/warp, MLP=16 fully-masked gather loop ----------
__global__ void __launch_bounds__(256) k_agg(const __nv_bfloat16* __restrict__ hs,
                                             const float* __restrict__ b,
                                             __nv_bfloat16* __restrict__ out) {
    int warp = (blockIdx.x * blockDim.x + threadIdx.x) >> 5;
    int lane = threadIdx.x & 31;
    if (warp >= NN) return;
    const uint2* hs2 = (const uint2*)hs;

    uint2 sv = hs2[(size_t)warp * 32 + lane];
    float2 s0 = bf2f(sv.x), s1 = bf2f(sv.y);
    float4 acc = make_float4(s0.x, s0.y, s1.x, s1.y);

    int e = g_rowptr[warp];
    int end = g_rowptr[warp + 1];

    // fully-masked loop: 16 idx loads, then 16 gathers, then adds.
    // out-of-range slots hit the zeroed dummy row NN (L1-resident after first touch).
    for (; e < end; e += 16) {
        int idx[16];
#pragma unroll
        for (int j = 0; j < 16; j++)
            idx[j] = (e + j < end) ? g_colsrc[e + j] : NN;
        uint2 v[16];
#pragma unroll
        for (int j = 0; j < 16; j++)
            v[j] = hs2[(size_t)idx[j] * 32 + lane];
#pragma unroll
        for (int j = 0; j < 16; j += 4) {
            float2 a0 = bf2f(v[j + 0].x), c0 = bf2f(v[j + 0].y);
            float2 a1 = bf2f(v[j + 1].x), c1 = bf2f(v[j + 1].y);
            float2 a2 = bf2f(v[j + 2].x), c2 = bf2f(v[j + 2].y);
            float2 a3 = bf2f(v[j + 3].x), c3 = bf2f(v[j + 3].y);
            acc.x += (a0.x + a1.x) + (a2.x + a3.x);
            acc.y += (a0.y + a1.y) + (a2.y + a3.y);
            acc.z += (c0.x + c1.x) + (c2.x + c3.x);
            acc.w += (c0.y + c1.y) + (c2.y + c3.y);
        }
    }

    float di = g_dinv[warp];
    float4 bb = ((const float4*)b)[lane];
    uint2 st;
    st.x = f2bf(elu_f(acc.x * di + bb.x), elu_f(acc.y * di + bb.y));
    st.y = f2bf(elu_f(acc.z * di + bb.z), elu_f(acc.w * di + bb.w));
    ((uint2*)out)[(size_t)warp * 32 + lane] = st;
}

// ---------- mean-pool ----------
#define POOL_NPB 256
__global__ void k_pool(const __nv_bfloat16* __restrict__ act, const int* __restrict__ batch) {
    int col = threadIdx.x;
    int start = blockIdx.x * POOL_NPB;
    if (start >= NN) return;
    int end = min(start + POOL_NPB, NN);
    float acc = 0.f;
    int cur = batch[start];
    int cl = 0;
    for (int i = start; i < end; i++) {
        int bb = batch[i];
        if (bb != cur) {
            atomicAdd(&g_sums[cur * HH + col], acc);
            if (col == 0) atomicAdd(&g_cnt[cur], cl);
            acc = 0.f; cl = 0; cur = bb;
        }
        acc += __bfloat162float(act[(size_t)i * HH + col]);
        cl++;
    }
    atomicAdd(&g_sums[cur * HH + col], acc);
    if (col == 0) atomicAdd(&g_cnt[cur], cl);
}

// ---------- classifier head ----------
__global__ void k_mlp(const float* __restrict__ Wc1, const float* __restrict__ bc1,
                      const float* __restrict__ Wc2, const float* __restrict__ bc2,
                      float* __restrict__ out) {
    __shared__ float gs[GG][129];
    int tid = threadIdx.x;
    for (int idx = tid; idx < GG * HH; idx += 256) {
        int g = idx >> 7, k = idx & 127;
        float c = fmaxf((float)g_cnt[g], 1.f);
        gs[g][k] = g_sums[idx] / c;
    }
    __syncthreads();
    int gid = tid >> 2;
    int q = tid & 3;
    float part = 0.f;
    for (int j = q * 16; j < q * 16 + 16; j++) {
        float z = bc1[j];
#pragma unroll 4
        for (int k = 0; k < 128; k++) z += gs[gid][k] * Wc1[k * 64 + j];
        part += fmaxf(z, 0.f) * Wc2[j];
    }
    part += __shfl_down_sync(0xffffffffu, part, 2);
    part += __shfl_down_sync(0xffffffffu, part, 1);
    if (q == 0) out[gid] = 1.f / (1.f + expf(-(part + bc2[0])));
}

// ---------- launch ----------
extern "C" void kernel_launch(void* const* d_in, const int* in_sizes, int n_in,
                              void* d_out, int out_size) {
    const float* x   = (const float*)d_in[0];
    const int*   ei  = (const int*)d_in[1];
    const int*   bat = (const int*)d_in[2];
    const float* W1  = (const float*)d_in[3];
    const float* b1  = (const float*)d_in[4];
    const float* W2  = (const float*)d_in[5];
    const float* b2  = (const float*)d_in[6];
    const float* W3  = (const float*)d_in[7];
    const float* b3  = (const float*)d_in[8];
    const float* Wc1 = (const float*)d_in[9];
    const float* bc1 = (const float*)d_in[10];
    const float* Wc2 = (const float*)d_in[11];
    const float* bc2 = (const float*)d_in[12];
    float* out = (float*)d_out;

    const int* src = ei;
    const int* dst = ei + EE;

    cudaFuncSetAttribute(k_gemm_x, cudaFuncAttributeMaxDynamicSharedMemorySize, GT_SMEM);
    cudaFuncSetAttribute(k_gemm_mma, cudaFuncAttributeMaxDynamicSharedMemorySize, GT_SMEM);

    void *pA, *pB, *pWh;
    cudaGetSymbolAddress(&pA, g_bufA);
    cudaGetSymbolAddress(&pB, g_bufB);
    cudaGetSymbolAddress(&pWh, g_whi);
    __nv_bfloat16* bufA = (__nv_bfloat16*)pA;
    __nv_bfloat16* bufB = (__nv_bfloat16*)pB;
    __nv_bfloat16* whi = (__nv_bfloat16*)pWh;

    // fork a second stream for the CSR chain (created/destroyed per call; capture-safe)
    cudaStream_t s2;
    cudaStreamCreateWithFlags(&s2, cudaStreamNonBlocking);
    cudaEvent_t evF, evJ;
    cudaEventCreateWithFlags(&evF, cudaEventDisableTiming);
    cudaEventCreateWithFlags(&evJ, cudaEventDisableTiming);

    cudaEventRecord(evF, 0);
    cudaStreamWaitEvent(s2, evF, 0);

    // stream 2: CSR build
    k_zdeg<<<(NN + 255) / 256, 256, 0, s2>>>();
    k_hist<<<(EE + 255) / 256, 256, 0, s2>>>(dst);
    k_scan1<<<SCAN_BLKS, 256, 0, s2>>>();
    k_scan3<<<SCAN_BLKS, 256, 0, s2>>>();
    k_fill<<<(EE + 255) / 256, 256, 0, s2>>>(src, dst);
    cudaEventRecord(evJ, s2);

    // main stream: feature path
    const int gemm_grid = (NN + 127) / 128;
    const int agg_grid  = (NN + 7) / 8;

    k_init_misc<<<64, 256>>>();
    k_prepw<<<192, 256>>>(W1, W2, W3);
    k_gemm_x<<<gemm_grid, 256, GT_SMEM>>>(x, whi, bufA);

    cudaStreamWaitEvent(0, evJ, 0);   // join: agg needs CSR + dinv

    k_agg<<<agg_grid, 256>>>(bufA, b1, bufB);
    k_gemm_mma<<<gemm_grid, 256, GT_SMEM>>>(bufB, whi + HH * HH, bufA);
    k_agg<<<agg_grid, 256>>>(bufA, b2, bufB);
    k_gemm_mma<<<gemm_grid, 256, GT_SMEM>>>(bufB, whi + 2 * HH * HH, bufA);
    k_agg<<<agg_grid, 256>>>(bufA, b3, bufB);

    k_pool<<<(NN + POOL_NPB - 1) / POOL_NPB, 128>>>(bufB, bat);
    k_mlp<<<1, 256>>>(Wc1, bc1, Wc2, bc2, out);

    cudaEventDestroy(evF);
    cudaEventDestroy(evJ);
    cudaStreamDestroy(s2);
}